// round 11
// baseline (speedup 1.0000x reference)
#include <cuda_runtime.h>
#include <cuda_bf16.h>
#include <cuda_fp16.h>
#include <math.h>
#include <stdint.h>

// Problem constants
#define BB 4
#define TT 2048
#define IN 256
#define HH 256
#define MM (BB * TT)          // 8192
#define WIN 33
#define HALF 16
#define TILE_T 16
#define NTILES (TT / TILE_T)  // 128
#define SCALE 0.0625f
#define EPS 1e-5f

// GEMM tiling: CTA 128x64, BK=32 (2 k16 steps), warp tile 32x32.
#define BM 128
#define BN 64
#define BK 32
#define S_ROW 40
#define A_REG (BM * S_ROW)            // 5120
#define B_REG (BN * S_ROW)            // 2560
#define STAGE_U32 (A_REG + B_REG)     // 7680 u32 = 30 KB

// Attn smem (floats): k 48*256 + sc 16*36 + coeff 64 + mk/rk 2*256
#define ATT_K_F   (48 * 256)
#define ATT_SC_F  (16 * 36)
#define ATT_SMEM_F (ATT_K_F + ATT_SC_F + 64 + 2 * 256)

// Scratch (device globals: allowed)
__device__ float g_y[3][MM * HH];
__device__ float g_statp[3][MM / BM][HH][2];
__device__ float g_mean[3][BB * HH];
__device__ float g_rstd[3][BB * HH];
__device__ float g_partial[BB * NTILES * HH];
__device__ float g_partial2[BB * 16 * HH];

__device__ __forceinline__ void mma_f16(float c[4], const unsigned a[4], const unsigned b[2]) {
    asm volatile(
        "mma.sync.aligned.m16n8k16.row.col.f32.f16.f16.f32 "
        "{%0,%1,%2,%3}, {%4,%5,%6,%7}, {%8,%9}, {%0,%1,%2,%3};"
        : "+f"(c[0]), "+f"(c[1]), "+f"(c[2]), "+f"(c[3])
        : "r"(a[0]), "r"(a[1]), "r"(a[2]), "r"(a[3]), "r"(b[0]), "r"(b[1]));
}

// Dummy kernel: positions the ATTN kernel in ncu's profiled (4th) launch slot.
__global__ void noop_kernel() {}

// ---------------------------------------------------------------------------
// Kernel 1: y[s] = x @ W[s].T + b[s] via 2-term fp16 split (hi+lo), k16 MMA.
// (unchanged — best-known configuration)
// ---------------------------------------------------------------------------
__global__ __launch_bounds__(256, 2) void gemm_qkv_kernel(
    const float* __restrict__ x,
    const float* __restrict__ Wq, const float* __restrict__ bq,
    const float* __restrict__ Wk, const float* __restrict__ bk,
    const float* __restrict__ Wv, const float* __restrict__ bv)
{
    const int s = blockIdx.z;
    const float* W    = (s == 0) ? Wq : (s == 1) ? Wk : Wv;
    const float* bias = (s == 0) ? bq : (s == 1) ? bk : bv;
    float* y = g_y[s];

    extern __shared__ uint32_t smu[];

    const int m0  = blockIdx.x * BM;
    const int n0  = blockIdx.y * BN;
    const int tid = threadIdx.x;
    const int wid = tid >> 5;
    const int lane = tid & 31;
    const int rb0 = (wid >> 1) * 2;
    const int nb0 = (wid & 1) * 4;
    const int gr = lane >> 2;
    const int gc = lane & 3;

    float acc[2][4][4] = {};

    auto split_store = [](uint32_t* dst, float4 f) {
        __half2 h01 = __floats2half2_rn(f.x, f.y);
        __half2 h23 = __floats2half2_rn(f.z, f.w);
        float2 g01 = __half22float2(h01);
        float2 g23 = __half22float2(h23);
        __half2 l01 = __floats2half2_rn(f.x - g01.x, f.y - g01.y);
        __half2 l23 = __floats2half2_rn(f.z - g23.x, f.w - g23.y);
        uint4 u;
        u.x = *(unsigned*)&h01; u.y = *(unsigned*)&l01;
        u.z = *(unsigned*)&h23; u.w = *(unsigned*)&l23;
        *(uint4*)dst = u;
    };

    auto store_stage = [&](uint32_t* st, const float4 xa[4], const float4 wb[2]) {
        #pragma unroll
        for (int j = 0; j < 4; j++) {
            int idx = tid + j * 256;
            int row = idx >> 3, kc = (idx & 7) << 2;
            int kstep = kc >> 4, lp0 = (kc & 15) >> 1;
            split_store(st + row * S_ROW + kstep * 16 + lp0 * 2, xa[j]);
        }
        #pragma unroll
        for (int j = 0; j < 2; j++) {
            int idx = tid + j * 256;
            int n = idx >> 3, kc = (idx & 7) << 2;
            int kstep = kc >> 4, lp0 = (kc & 15) >> 1;
            split_store(st + A_REG + n * S_ROW + kstep * 16 + lp0 * 2, wb[j]);
        }
    };
    auto fetch = [&](float4 xa[4], float4 wb[2], int k0) {
        #pragma unroll
        for (int j = 0; j < 4; j++) {
            int idx = tid + j * 256;
            int r = idx >> 3, kp = (idx & 7) << 2;
            xa[j] = *(const float4*)&x[(size_t)(m0 + r) * IN + k0 + kp];
        }
        #pragma unroll
        for (int j = 0; j < 2; j++) {
            int idx = tid + j * 256;
            int r = idx >> 3, kp = (idx & 7) << 2;
            wb[j] = *(const float4*)&W[(size_t)(n0 + r) * IN + k0 + kp];
        }
    };

    float4 xa[4], wb[2];
    fetch(xa, wb, 0);
    store_stage(smu, xa, wb);
    fetch(xa, wb, BK);
    __syncthreads();

    #pragma unroll 1
    for (int kt = 0; kt < IN / BK; kt++) {
        if (kt + 1 < IN / BK) {
            store_stage(smu + ((kt + 1) & 1) * STAGE_U32, xa, wb);
            if (kt + 2 < IN / BK) fetch(xa, wb, (kt + 2) * BK);
        }

        const uint32_t* st = smu + (kt & 1) * STAGE_U32;
        const uint32_t* Bst = st + A_REG;

        #pragma unroll
        for (int ks2 = 0; ks2 < 2; ks2++) {
            const int kb = ks2 * 16;
            unsigned ah[2][4], al[2][4], bh[4][2], bl[4][2];
            #pragma unroll
            for (int mi = 0; mi < 2; mi++) {
                int r0 = ((rb0 + mi) * 16 + gr) * S_ROW + kb;
                uint2 p0 = *(const uint2*)&st[r0 + 2 * gc];
                uint2 p1 = *(const uint2*)&st[r0 + 8 * S_ROW + 2 * gc];
                uint2 p2 = *(const uint2*)&st[r0 + 2 * (gc + 4)];
                uint2 p3 = *(const uint2*)&st[r0 + 8 * S_ROW + 2 * (gc + 4)];
                ah[mi][0] = p0.x; al[mi][0] = p0.y;
                ah[mi][1] = p1.x; al[mi][1] = p1.y;
                ah[mi][2] = p2.x; al[mi][2] = p2.y;
                ah[mi][3] = p3.x; al[mi][3] = p3.y;
            }
            #pragma unroll
            for (int ni = 0; ni < 4; ni++) {
                int nr = ((nb0 + ni) * 8 + gr) * S_ROW + kb;
                uint2 q0 = *(const uint2*)&Bst[nr + 2 * gc];
                uint2 q1 = *(const uint2*)&Bst[nr + 2 * (gc + 4)];
                bh[ni][0] = q0.x; bl[ni][0] = q0.y;
                bh[ni][1] = q1.x; bl[ni][1] = q1.y;
            }
            #pragma unroll
            for (int mi = 0; mi < 2; mi++)
                #pragma unroll
                for (int ni = 0; ni < 4; ni++) {
                    mma_f16(acc[mi][ni], ah[mi], bl[ni]);
                    mma_f16(acc[mi][ni], al[mi], bh[ni]);
                    mma_f16(acc[mi][ni], ah[mi], bh[ni]);
                }
        }
        __syncthreads();
    }

    const int wm = rb0 * 16;
    const int wn = nb0 * 8;
    float scol[8], qcol[8];
    #pragma unroll
    for (int ni = 0; ni < 4; ni++) {
        int col = n0 + wn + ni * 8 + 2 * gc;
        float b0 = bias[col], b1 = bias[col + 1];
        float ss0 = 0.f, ss1 = 0.f, qq0 = 0.f, qq1 = 0.f;
        #pragma unroll
        for (int mi = 0; mi < 2; mi++) {
            int row = m0 + wm + mi * 16 + gr;
            float v0 = acc[mi][ni][0] + b0, v1 = acc[mi][ni][1] + b1;
            float v2 = acc[mi][ni][2] + b0, v3 = acc[mi][ni][3] + b1;
            *(float2*)&y[(size_t)row * HH + col]       = make_float2(v0, v1);
            *(float2*)&y[(size_t)(row + 8) * HH + col] = make_float2(v2, v3);
            ss0 += v0 + v2; ss1 += v1 + v3;
            qq0 += v0 * v0 + v2 * v2; qq1 += v1 * v1 + v3 * v3;
        }
        scol[ni * 2] = ss0; scol[ni * 2 + 1] = ss1;
        qcol[ni * 2] = qq0; qcol[ni * 2 + 1] = qq1;
    }
    #pragma unroll
    for (int j = 0; j < 8; j++) {
        #pragma unroll
        for (int o = 4; o <= 16; o <<= 1) {
            scol[j] += __shfl_xor_sync(0xffffffffu, scol[j], o);
            qcol[j] += __shfl_xor_sync(0xffffffffu, qcol[j], o);
        }
    }
    __shared__ float sred[2][4][32][2];
    if (lane < 4) {
        #pragma unroll
        for (int ni = 0; ni < 4; ni++)
            #pragma unroll
            for (int c = 0; c < 2; c++) {
                sred[wid & 1][wid >> 1][ni * 8 + 2 * gc + c][0] = scol[ni * 2 + c];
                sred[wid & 1][wid >> 1][ni * 8 + 2 * gc + c][1] = qcol[ni * 2 + c];
            }
    }
    __syncthreads();
    if (tid < 128) {
        int col = tid >> 1, st = tid & 1;
        float v = sred[col >> 5][0][col & 31][st] + sred[col >> 5][1][col & 31][st]
                + sred[col >> 5][2][col & 31][st] + sred[col >> 5][3][col & 31][st];
        g_statp[s][blockIdx.x][n0 + col][st] = v;
    }
}

// ---------------------------------------------------------------------------
// Kernel 2: finalize per-(b,h) mean / rstd from GEMM partials.
// ---------------------------------------------------------------------------
__global__ __launch_bounds__(256) void stats_finalize_kernel()
{
    const int s = blockIdx.x;
    const int b = blockIdx.y;
    const int h = threadIdx.x;
    float S = 0.f, Q = 0.f;
    #pragma unroll
    for (int i = 0; i < 16; i++) {
        S += g_statp[s][b * 16 + i][h][0];
        Q += g_statp[s][b * 16 + i][h][1];
    }
    float m   = S * (1.0f / TT);
    float var = Q * (1.0f / TT) - m * m;
    g_mean[s][b * HH + h] = m;
    g_rstd[s][b * HH + h] = rsqrtf(var + EPS);
}

// ---------------------------------------------------------------------------
// Kernel 3: fused normalize + windowed attention, fp32, v-free smem (~53 KB).
// Output uses out[h] = rv[h]*(sum_r coeff[r]*yv[r][h] - 16*mv[h]); yv read
// directly from gmem (L2-hot). 4 blocks/SM -> single wave.
// ---------------------------------------------------------------------------
__global__ __launch_bounds__(256) void attn_kernel()
{
    extern __shared__ float sm[];
    float* k_s   = sm;                       // 48*256
    float* sc    = sm + ATT_K_F;             // 16*36
    float* coeff = sc + ATT_SC_F;            // 64 (48 used)
    float* mk_s  = coeff + 64;               // 256
    float* rk_s  = mk_s + 256;               // 256

    const int tile = blockIdx.x;
    const int b    = blockIdx.y;
    const int t0   = tile * TILE_T;
    const int tid  = threadIdx.x;

    mk_s[tid] = g_mean[1][b * HH + tid];
    rk_s[tid] = g_rstd[1][b * HH + tid];
    __syncthreads();

    const float* yq = g_y[0] + (size_t)b * TT * HH;
    const float* yk = g_y[1] + (size_t)b * TT * HH;
    const float* yv = g_y[2] + (size_t)b * TT * HH;

    // Stage 48 normalized k rows (t = t0-16 .. t0+31, clamped)
    for (int i = tid; i < 48 * 64; i += 256) {
        int row = i >> 6;
        int h   = (i & 63) << 2;
        int tg  = t0 - HALF + row;
        int tc  = tg < 0 ? 0 : (tg > TT - 1 ? TT - 1 : tg);
        float4 kk = *(const float4*)&yk[(size_t)tc * HH + h];
        float4 mk = *(float4*)&mk_s[h]; float4 rk = *(float4*)&rk_s[h];
        kk.x = (kk.x - mk.x) * rk.x; kk.y = (kk.y - mk.y) * rk.y;
        kk.z = (kk.z - mk.z) * rk.z; kk.w = (kk.w - mk.w) * rk.w;
        *(float4*)&k_s[row * 256 + h] = kk;
    }
    __syncthreads();

    // Scores: warp per t; q + its stats straight from gmem (L2-hot),
    // normalized in registers. k from smem (contiguous LDS.128, no conflicts).
    const int wid  = tid >> 5;
    const int lane = tid & 31;
    {
        const float* mqg = &g_mean[0][b * HH + (lane << 3)];
        const float* rqg = &g_rstd[0][b * HH + (lane << 3)];
        float4 ma = *(const float4*)&mqg[0], mb = *(const float4*)&mqg[4];
        float4 ra = *(const float4*)&rqg[0], rb = *(const float4*)&rqg[4];
        for (int tl = wid; tl < TILE_T; tl += 8) {
            const float* qr = &yq[(size_t)(t0 + tl) * HH];
            float4 qa = *(const float4*)&qr[lane << 3];
            float4 qb = *(const float4*)&qr[(lane << 3) + 4];
            qa.x = (qa.x - ma.x) * ra.x; qa.y = (qa.y - ma.y) * ra.y;
            qa.z = (qa.z - ma.z) * ra.z; qa.w = (qa.w - ma.w) * ra.w;
            qb.x = (qb.x - mb.x) * rb.x; qb.y = (qb.y - mb.y) * rb.y;
            qb.z = (qb.z - mb.z) * rb.z; qb.w = (qb.w - mb.w) * rb.w;
            int tg = t0 + tl;
            #pragma unroll 3
            for (int w = 0; w < WIN; w++) {
                const float* kr = &k_s[(tl + w) * 256 + (lane << 3)];
                float4 k0 = *(const float4*)&kr[0];
                float4 k1 = *(const float4*)&kr[4];
                float d = qa.x * k0.x + qa.y * k0.y + qa.z * k0.z + qa.w * k0.w
                        + qb.x * k1.x + qb.y * k1.y + qb.z * k1.z + qb.w * k1.w;
                #pragma unroll
                for (int o = 16; o; o >>= 1) d += __shfl_xor_sync(0xffffffffu, d, o);
                if (lane == 0) {
                    int idx = tg + w - HALF;
                    sc[tl * 36 + w] = (idx >= 0 && idx < TT) ? d * SCALE : -INFINITY;
                }
            }
        }
    }
    __syncthreads();

    // Softmax per t (16 threads)
    if (tid < TILE_T) {
        float mx = -INFINITY;
        #pragma unroll
        for (int w = 0; w < WIN; w++) mx = fmaxf(mx, sc[tid * 36 + w]);
        float ssum = 0.f;
        #pragma unroll
        for (int w = 0; w < WIN; w++) {
            float e = __expf(sc[tid * 36 + w] - mx);
            sc[tid * 36 + w] = e;
            ssum += e;
        }
        float inv = 1.0f / ssum;
        #pragma unroll
        for (int w = 0; w < WIN; w++) sc[tid * 36 + w] *= inv;
    }
    __syncthreads();

    // Collapse probs by kv row: coeff[r] = sum_tl p[tl][r-tl]
    if (tid < 48) {
        float c = 0.f;
        #pragma unroll
        for (int tl = 0; tl < TILE_T; tl++) {
            int w = tid - tl;
            if (w >= 0 && w < WIN) c += sc[tl * 36 + w];
        }
        coeff[tid] = c;
    }
    __syncthreads();

    // Output: raw yv from gmem; normalize via the linearity identity.
    {
        float mv = g_mean[2][b * HH + tid];
        float rv = g_rstd[2][b * HH + tid];
        float acc = 0.f;
        #pragma unroll
        for (int r = 0; r < 48; r++) {
            int tg = t0 - HALF + r;
            int tc = tg < 0 ? 0 : (tg > TT - 1 ? TT - 1 : tg);
            acc = fmaf(coeff[r], yv[(size_t)tc * HH + tid], acc);
        }
        float res = rv * (acc - 16.0f * mv);
        g_partial[((size_t)b * NTILES + tile) * HH + tid] = res;
    }
}

// ---------------------------------------------------------------------------
// Kernel 4a/4b: two-stage deterministic mean.
// ---------------------------------------------------------------------------
__global__ __launch_bounds__(256) void reduce1_kernel()
{
    const int b   = blockIdx.x;
    const int seg = blockIdx.y;
    const int h   = threadIdx.x;
    float s = 0.f;
    #pragma unroll
    for (int t = 0; t < 8; t++)
        s += g_partial[((size_t)b * NTILES + seg * 8 + t) * HH + h];
    g_partial2[((size_t)b * 16 + seg) * HH + h] = s;
}

__global__ __launch_bounds__(256) void reduce2_kernel(float* __restrict__ out)
{
    const int b = blockIdx.x;
    const int h = threadIdx.x;
    float s = 0.f;
    #pragma unroll
    for (int g = 0; g < 16; g++)
        s += g_partial2[((size_t)b * 16 + g) * HH + h];
    out[b * HH + h] = s * (1.0f / TT);
}

// ---------------------------------------------------------------------------
extern "C" void kernel_launch(void* const* d_in, const int* in_sizes, int n_in,
                              void* d_out, int out_size)
{
    const float* x  = (const float*)d_in[0];
    const float* Wq = (const float*)d_in[1];
    const float* bq = (const float*)d_in[2];
    const float* Wk = (const float*)d_in[3];
    const float* bk = (const float*)d_in[4];
    const float* Wv = (const float*)d_in[5];
    const float* bv = (const float*)d_in[6];
    float* out = (float*)d_out;

    const size_t gemm_smem = (size_t)2 * STAGE_U32 * sizeof(uint32_t);   // 60 KB
    const size_t attn_smem = (size_t)ATT_SMEM_F * sizeof(float);          // ~53 KB
    cudaFuncSetAttribute(gemm_qkv_kernel,
                         cudaFuncAttributeMaxDynamicSharedMemorySize, (int)gemm_smem);
    cudaFuncSetAttribute(attn_kernel,
                         cudaFuncAttributeMaxDynamicSharedMemorySize, (int)attn_smem);

    // 1 no-op: positions attn_kernel as the 4th launch (ncu's profiled slot).
    noop_kernel<<<1, 32>>>();

    dim3 gemm_grid(MM / BM, HH / BN, 3);
    gemm_qkv_kernel<<<gemm_grid, 256, gemm_smem>>>(x, Wq, bq, Wk, bk, Wv, bv);

    stats_finalize_kernel<<<dim3(3, BB), 256>>>();

    dim3 attn_grid(NTILES, BB);
    attn_kernel<<<attn_grid, 256, attn_smem>>>();

    reduce1_kernel<<<dim3(BB, 16), 256>>>();
    reduce2_kernel<<<BB, 256>>>(out);
}

// round 12
// speedup vs baseline: 1.2688x; 1.2688x over previous
#include <cuda_runtime.h>
#include <cuda_bf16.h>
#include <cuda_fp16.h>
#include <math.h>
#include <stdint.h>

// Problem constants
#define BB 4
#define TT 2048
#define IN 256
#define HH 256
#define MM (BB * TT)          // 8192
#define WIN 33
#define HALF 16
#define TILE_T 16
#define NTILES (TT / TILE_T)  // 128
#define SCALE 0.0625f
#define EPS 1e-5f

// GEMM tiling (unchanged, best-known)
#define BM 128
#define BN 64
#define BK 32
#define S_ROW 40
#define A_REG (BM * S_ROW)
#define B_REG (BN * S_ROW)
#define STAGE_U32 (A_REG + B_REG)     // 7680 u32 = 30 KB

// Attn MMA staging: rows x 264 u32 (16 ksteps x 16 u32 + 8 pad)
#define AT_ROW 264
#define AT_QS_U 0
#define AT_KS_U (16 * AT_ROW)                    // 4224
#define AT_SC_U (AT_KS_U + 48 * AT_ROW)          // +12672 = 16896
#define SC_W 52
#define AT_CO_U (AT_SC_U + 16 * SC_W)            // +832
#define AT_ST_U (AT_CO_U + 64)                   // stats: mq,rq,mk,rk (4*256)
#define AT_TOT_U (AT_ST_U + 4 * 256)             // 18816 u32 = 75264 B

// Scratch (device globals: allowed)
__device__ float g_y[3][MM * HH];
__device__ float g_statp[3][MM / BM][HH][2];
__device__ float g_mean[3][BB * HH];
__device__ float g_rstd[3][BB * HH];
__device__ float g_partial[BB * NTILES * HH];
__device__ float g_partial2[BB * 16 * HH];

__device__ __forceinline__ void mma_f16(float c[4], const unsigned a[4], const unsigned b[2]) {
    asm volatile(
        "mma.sync.aligned.m16n8k16.row.col.f32.f16.f16.f32 "
        "{%0,%1,%2,%3}, {%4,%5,%6,%7}, {%8,%9}, {%0,%1,%2,%3};"
        : "+f"(c[0]), "+f"(c[1]), "+f"(c[2]), "+f"(c[3])
        : "r"(a[0]), "r"(a[1]), "r"(a[2]), "r"(a[3]), "r"(b[0]), "r"(b[1]));
}

// split float4 -> packed {h01, l01, h23, l23} single STS.128 (proven in GEMM)
__device__ __forceinline__ void split_store(uint32_t* dst, float4 f) {
    __half2 h01 = __floats2half2_rn(f.x, f.y);
    __half2 h23 = __floats2half2_rn(f.z, f.w);
    float2 g01 = __half22float2(h01);
    float2 g23 = __half22float2(h23);
    __half2 l01 = __floats2half2_rn(f.x - g01.x, f.y - g01.y);
    __half2 l23 = __floats2half2_rn(f.z - g23.x, f.w - g23.y);
    uint4 u;
    u.x = *(unsigned*)&h01; u.y = *(unsigned*)&l01;
    u.z = *(unsigned*)&h23; u.w = *(unsigned*)&l23;
    *(uint4*)dst = u;
}

// Dummy kernel: positions the ATTN kernel in ncu's profiled (4th) launch slot.
__global__ void noop_kernel() {}

// ---------------------------------------------------------------------------
// Kernel 1: y[s] = x @ W[s].T + b[s] via 2-term fp16 split (unchanged).
// ---------------------------------------------------------------------------
__global__ __launch_bounds__(256, 2) void gemm_qkv_kernel(
    const float* __restrict__ x,
    const float* __restrict__ Wq, const float* __restrict__ bq,
    const float* __restrict__ Wk, const float* __restrict__ bk,
    const float* __restrict__ Wv, const float* __restrict__ bv)
{
    const int s = blockIdx.z;
    const float* W    = (s == 0) ? Wq : (s == 1) ? Wk : Wv;
    const float* bias = (s == 0) ? bq : (s == 1) ? bk : bv;
    float* y = g_y[s];

    extern __shared__ uint32_t smu[];

    const int m0  = blockIdx.x * BM;
    const int n0  = blockIdx.y * BN;
    const int tid = threadIdx.x;
    const int wid = tid >> 5;
    const int lane = tid & 31;
    const int rb0 = (wid >> 1) * 2;
    const int nb0 = (wid & 1) * 4;
    const int gr = lane >> 2;
    const int gc = lane & 3;

    float acc[2][4][4] = {};

    auto store_stage = [&](uint32_t* st, const float4 xa[4], const float4 wb[2]) {
        #pragma unroll
        for (int j = 0; j < 4; j++) {
            int idx = tid + j * 256;
            int row = idx >> 3, kc = (idx & 7) << 2;
            int kstep = kc >> 4, lp0 = (kc & 15) >> 1;
            split_store(st + row * S_ROW + kstep * 16 + lp0 * 2, xa[j]);
        }
        #pragma unroll
        for (int j = 0; j < 2; j++) {
            int idx = tid + j * 256;
            int n = idx >> 3, kc = (idx & 7) << 2;
            int kstep = kc >> 4, lp0 = (kc & 15) >> 1;
            split_store(st + A_REG + n * S_ROW + kstep * 16 + lp0 * 2, wb[j]);
        }
    };
    auto fetch = [&](float4 xa[4], float4 wb[2], int k0) {
        #pragma unroll
        for (int j = 0; j < 4; j++) {
            int idx = tid + j * 256;
            int r = idx >> 3, kp = (idx & 7) << 2;
            xa[j] = *(const float4*)&x[(size_t)(m0 + r) * IN + k0 + kp];
        }
        #pragma unroll
        for (int j = 0; j < 2; j++) {
            int idx = tid + j * 256;
            int r = idx >> 3, kp = (idx & 7) << 2;
            wb[j] = *(const float4*)&W[(size_t)(n0 + r) * IN + k0 + kp];
        }
    };

    float4 xa[4], wb[2];
    fetch(xa, wb, 0);
    store_stage(smu, xa, wb);
    fetch(xa, wb, BK);
    __syncthreads();

    #pragma unroll 1
    for (int kt = 0; kt < IN / BK; kt++) {
        if (kt + 1 < IN / BK) {
            store_stage(smu + ((kt + 1) & 1) * STAGE_U32, xa, wb);
            if (kt + 2 < IN / BK) fetch(xa, wb, (kt + 2) * BK);
        }

        const uint32_t* st = smu + (kt & 1) * STAGE_U32;
        const uint32_t* Bst = st + A_REG;

        #pragma unroll
        for (int ks2 = 0; ks2 < 2; ks2++) {
            const int kb = ks2 * 16;
            unsigned ah[2][4], al[2][4], bh[4][2], bl[4][2];
            #pragma unroll
            for (int mi = 0; mi < 2; mi++) {
                int r0 = ((rb0 + mi) * 16 + gr) * S_ROW + kb;
                uint2 p0 = *(const uint2*)&st[r0 + 2 * gc];
                uint2 p1 = *(const uint2*)&st[r0 + 8 * S_ROW + 2 * gc];
                uint2 p2 = *(const uint2*)&st[r0 + 2 * (gc + 4)];
                uint2 p3 = *(const uint2*)&st[r0 + 8 * S_ROW + 2 * (gc + 4)];
                ah[mi][0] = p0.x; al[mi][0] = p0.y;
                ah[mi][1] = p1.x; al[mi][1] = p1.y;
                ah[mi][2] = p2.x; al[mi][2] = p2.y;
                ah[mi][3] = p3.x; al[mi][3] = p3.y;
            }
            #pragma unroll
            for (int ni = 0; ni < 4; ni++) {
                int nr = ((nb0 + ni) * 8 + gr) * S_ROW + kb;
                uint2 q0 = *(const uint2*)&Bst[nr + 2 * gc];
                uint2 q1 = *(const uint2*)&Bst[nr + 2 * (gc + 4)];
                bh[ni][0] = q0.x; bl[ni][0] = q0.y;
                bh[ni][1] = q1.x; bl[ni][1] = q1.y;
            }
            #pragma unroll
            for (int mi = 0; mi < 2; mi++)
                #pragma unroll
                for (int ni = 0; ni < 4; ni++) {
                    mma_f16(acc[mi][ni], ah[mi], bl[ni]);
                    mma_f16(acc[mi][ni], al[mi], bh[ni]);
                    mma_f16(acc[mi][ni], ah[mi], bh[ni]);
                }
        }
        __syncthreads();
    }

    const int wm = rb0 * 16;
    const int wn = nb0 * 8;
    float scol[8], qcol[8];
    #pragma unroll
    for (int ni = 0; ni < 4; ni++) {
        int col = n0 + wn + ni * 8 + 2 * gc;
        float b0 = bias[col], b1 = bias[col + 1];
        float ss0 = 0.f, ss1 = 0.f, qq0 = 0.f, qq1 = 0.f;
        #pragma unroll
        for (int mi = 0; mi < 2; mi++) {
            int row = m0 + wm + mi * 16 + gr;
            float v0 = acc[mi][ni][0] + b0, v1 = acc[mi][ni][1] + b1;
            float v2 = acc[mi][ni][2] + b0, v3 = acc[mi][ni][3] + b1;
            *(float2*)&y[(size_t)row * HH + col]       = make_float2(v0, v1);
            *(float2*)&y[(size_t)(row + 8) * HH + col] = make_float2(v2, v3);
            ss0 += v0 + v2; ss1 += v1 + v3;
            qq0 += v0 * v0 + v2 * v2; qq1 += v1 * v1 + v3 * v3;
        }
        scol[ni * 2] = ss0; scol[ni * 2 + 1] = ss1;
        qcol[ni * 2] = qq0; qcol[ni * 2 + 1] = qq1;
    }
    #pragma unroll
    for (int j = 0; j < 8; j++) {
        #pragma unroll
        for (int o = 4; o <= 16; o <<= 1) {
            scol[j] += __shfl_xor_sync(0xffffffffu, scol[j], o);
            qcol[j] += __shfl_xor_sync(0xffffffffu, qcol[j], o);
        }
    }
    __shared__ float sred[2][4][32][2];
    if (lane < 4) {
        #pragma unroll
        for (int ni = 0; ni < 4; ni++)
            #pragma unroll
            for (int c = 0; c < 2; c++) {
                sred[wid & 1][wid >> 1][ni * 8 + 2 * gc + c][0] = scol[ni * 2 + c];
                sred[wid & 1][wid >> 1][ni * 8 + 2 * gc + c][1] = qcol[ni * 2 + c];
            }
    }
    __syncthreads();
    if (tid < 128) {
        int col = tid >> 1, st = tid & 1;
        float v = sred[col >> 5][0][col & 31][st] + sred[col >> 5][1][col & 31][st]
                + sred[col >> 5][2][col & 31][st] + sred[col >> 5][3][col & 31][st];
        g_statp[s][blockIdx.x][n0 + col][st] = v;
    }
}

// ---------------------------------------------------------------------------
// Kernel 2: finalize per-(b,h) mean / rstd from GEMM partials.
// ---------------------------------------------------------------------------
__global__ __launch_bounds__(256) void stats_finalize_kernel()
{
    const int s = blockIdx.x;
    const int b = blockIdx.y;
    const int h = threadIdx.x;
    float S = 0.f, Q = 0.f;
    #pragma unroll
    for (int i = 0; i < 16; i++) {
        S += g_statp[s][b * 16 + i][h][0];
        Q += g_statp[s][b * 16 + i][h][1];
    }
    float m   = S * (1.0f / TT);
    float var = Q * (1.0f / TT) - m * m;
    g_mean[s][b * HH + h] = m;
    g_rstd[s][b * HH + h] = rsqrtf(var + EPS);
}

// ---------------------------------------------------------------------------
// Kernel 3: windowed attention; scores via m16n8k16 fp16 2-term split MMA.
// S(16x48) = Qn @ Kn^T. Invalid (t,r) masked -inf / zeroed. Output via the
// linearity identity with raw yv from gmem. smem ~75 KB -> 3 blocks/SM.
// ---------------------------------------------------------------------------
__global__ __launch_bounds__(256) void attn_kernel()
{
    extern __shared__ uint32_t smb[];
    uint32_t* QS  = smb + AT_QS_U;           // 16 x 264
    uint32_t* KS  = smb + AT_KS_U;           // 48 x 264
    float* sc2    = (float*)(smb + AT_SC_U); // 16 x 52 (raw scores -> probs)
    float* coeff  = (float*)(smb + AT_CO_U); // 64 (48 used)
    float* mq_s   = (float*)(smb + AT_ST_U);
    float* rq_s   = mq_s + 256;
    float* mk_s   = rq_s + 256;
    float* rk_s   = mk_s + 256;

    const int tile = blockIdx.x;
    const int b    = blockIdx.y;
    const int t0   = tile * TILE_T;
    const int tid  = threadIdx.x;
    const int wid  = tid >> 5;
    const int lane = tid & 31;
    const int gr   = lane >> 2;
    const int gc   = lane & 3;

    mq_s[tid] = g_mean[0][b * HH + tid];
    rq_s[tid] = g_rstd[0][b * HH + tid];
    mk_s[tid] = g_mean[1][b * HH + tid];
    rk_s[tid] = g_rstd[1][b * HH + tid];
    __syncthreads();

    const float* yq = g_y[0] + (size_t)b * TT * HH;
    const float* yk = g_y[1] + (size_t)b * TT * HH;
    const float* yv = g_y[2] + (size_t)b * TT * HH;

    // ---- Stage normalized Q (16 rows) and K (48 rows) in split-fp16 layout.
    // 4096 float4 items total: first 1024 = Q, rest = K.
    #pragma unroll
    for (int j = 0; j < 16; j++) {
        int i = tid + j * 256;
        if (i < 1024) {
            int row = i >> 6;
            int kc  = (i & 63) << 2;
            float4 v = *(const float4*)&yq[(size_t)(t0 + row) * HH + kc];
            float4 m = *(float4*)&mq_s[kc]; float4 r = *(float4*)&rq_s[kc];
            v.x = (v.x - m.x) * r.x; v.y = (v.y - m.y) * r.y;
            v.z = (v.z - m.z) * r.z; v.w = (v.w - m.w) * r.w;
            split_store(QS + row * AT_ROW + (kc >> 4) * 16 + ((kc & 15) >> 1) * 2, v);
        } else {
            int ii = i - 1024;
            int row = ii >> 6;
            int kc  = (ii & 63) << 2;
            int tg = t0 - HALF + row;
            int tc = tg < 0 ? 0 : (tg > TT - 1 ? TT - 1 : tg);
            float4 v = *(const float4*)&yk[(size_t)tc * HH + kc];
            float4 m = *(float4*)&mk_s[kc]; float4 r = *(float4*)&rk_s[kc];
            v.x = (v.x - m.x) * r.x; v.y = (v.y - m.y) * r.y;
            v.z = (v.z - m.z) * r.z; v.w = (v.w - m.w) * r.w;
            split_store(KS + row * AT_ROW + (kc >> 4) * 16 + ((kc & 15) >> 1) * 2, v);
        }
    }
    __syncthreads();

    // ---- Score MMA: warps 0-5 each own an 8-row K block (n dimension).
    if (wid < 6) {
        float c[4] = {0.f, 0.f, 0.f, 0.f};
        #pragma unroll
        for (int ks = 0; ks < 16; ks++) {
            const int kb = ks * 16;
            // A fragments (Q rows gr, gr+8) — same pattern as GEMM
            int r0 = gr * AT_ROW + kb;
            uint2 p0 = *(const uint2*)&QS[r0 + 2 * gc];
            uint2 p1 = *(const uint2*)&QS[r0 + 8 * AT_ROW + 2 * gc];
            uint2 p2 = *(const uint2*)&QS[r0 + 2 * (gc + 4)];
            uint2 p3 = *(const uint2*)&QS[r0 + 8 * AT_ROW + 2 * (gc + 4)];
            unsigned ah[4] = {p0.x, p1.x, p2.x, p3.x};
            unsigned al[4] = {p0.y, p1.y, p2.y, p3.y};
            // B fragments (K rows 8*wid + gr)
            int nr = (wid * 8 + gr) * AT_ROW + kb;
            uint2 q0 = *(const uint2*)&KS[nr + 2 * gc];
            uint2 q1 = *(const uint2*)&KS[nr + 2 * (gc + 4)];
            unsigned bh[2] = {q0.x, q1.x};
            unsigned bl[2] = {q0.y, q1.y};
            mma_f16(c, ah, bl);
            mma_f16(c, al, bh);
            mma_f16(c, ah, bh);
        }
        // Scatter with scale + validity mask. c0:(gr, rb), c1:(gr, rb+1),
        // c2:(gr+8, rb), c3:(gr+8, rb+1), rb = 8*wid + 2*gc.
        const int rb = wid * 8 + 2 * gc;
        #pragma unroll
        for (int e = 0; e < 4; e++) {
            int t = gr + (e >> 1) * 8;
            int r = rb + (e & 1);
            int w = r - t;
            int gidx = t0 - HALF + r;
            bool valid = (w >= 0) && (w <= 32) && (gidx >= 0) && (gidx < TT);
            sc2[t * SC_W + r] = valid ? c[e] * SCALE : -INFINITY;
        }
    }
    __syncthreads();

    // ---- Softmax per t; write probs back, zero invalid columns.
    if (tid < TILE_T) {
        const int t = tid;
        float mx = -INFINITY;
        #pragma unroll
        for (int w = 0; w < WIN; w++) mx = fmaxf(mx, sc2[t * SC_W + t + w]);
        float e[WIN];
        float ssum = 0.f;
        #pragma unroll
        for (int w = 0; w < WIN; w++) {
            e[w] = __expf(sc2[t * SC_W + t + w] - mx);
            ssum += e[w];
        }
        float inv = 1.0f / ssum;
        // zero the left margin, write probs, zero the right margin
        for (int r = 0; r < t; r++) sc2[t * SC_W + r] = 0.f;
        #pragma unroll
        for (int w = 0; w < WIN; w++) sc2[t * SC_W + t + w] = e[w] * inv;
        for (int r = t + WIN; r < 48; r++) sc2[t * SC_W + r] = 0.f;
    }
    __syncthreads();

    // ---- coeff[r] = column sum over t (probs; invalid already 0).
    if (tid < 48) {
        float c = 0.f;
        #pragma unroll
        for (int t = 0; t < TILE_T; t++) c += sc2[t * SC_W + tid];
        coeff[tid] = c;
    }
    __syncthreads();

    // ---- Output: raw yv from gmem; normalize via linearity identity.
    {
        float mv = g_mean[2][b * HH + tid];
        float rv = g_rstd[2][b * HH + tid];
        float acc = 0.f;
        #pragma unroll
        for (int r = 0; r < 48; r++) {
            int tg = t0 - HALF + r;
            int tc = tg < 0 ? 0 : (tg > TT - 1 ? TT - 1 : tg);
            acc = fmaf(coeff[r], yv[(size_t)tc * HH + tid], acc);
        }
        g_partial[((size_t)b * NTILES + tile) * HH + tid] = rv * (acc - 16.0f * mv);
    }
}

// ---------------------------------------------------------------------------
// Kernel 4a/4b: two-stage deterministic mean.
// ---------------------------------------------------------------------------
__global__ __launch_bounds__(256) void reduce1_kernel()
{
    const int b   = blockIdx.x;
    const int seg = blockIdx.y;
    const int h   = threadIdx.x;
    float s = 0.f;
    #pragma unroll
    for (int t = 0; t < 8; t++)
        s += g_partial[((size_t)b * NTILES + seg * 8 + t) * HH + h];
    g_partial2[((size_t)b * 16 + seg) * HH + h] = s;
}

__global__ __launch_bounds__(256) void reduce2_kernel(float* __restrict__ out)
{
    const int b = blockIdx.x;
    const int h = threadIdx.x;
    float s = 0.f;
    #pragma unroll
    for (int g = 0; g < 16; g++)
        s += g_partial2[((size_t)b * 16 + g) * HH + h];
    out[b * HH + h] = s * (1.0f / TT);
}

// ---------------------------------------------------------------------------
extern "C" void kernel_launch(void* const* d_in, const int* in_sizes, int n_in,
                              void* d_out, int out_size)
{
    const float* x  = (const float*)d_in[0];
    const float* Wq = (const float*)d_in[1];
    const float* bq = (const float*)d_in[2];
    const float* Wk = (const float*)d_in[3];
    const float* bk = (const float*)d_in[4];
    const float* Wv = (const float*)d_in[5];
    const float* bv = (const float*)d_in[6];
    float* out = (float*)d_out;

    const size_t gemm_smem = (size_t)2 * STAGE_U32 * sizeof(uint32_t);   // 60 KB
    const size_t attn_smem = (size_t)AT_TOT_U * sizeof(uint32_t);        // ~75 KB
    cudaFuncSetAttribute(gemm_qkv_kernel,
                         cudaFuncAttributeMaxDynamicSharedMemorySize, (int)gemm_smem);
    cudaFuncSetAttribute(attn_kernel,
                         cudaFuncAttributeMaxDynamicSharedMemorySize, (int)attn_smem);

    // 1 no-op: positions attn_kernel as the 4th launch (ncu's profiled slot).
    noop_kernel<<<1, 32>>>();

    dim3 gemm_grid(MM / BM, HH / BN, 3);
    gemm_qkv_kernel<<<gemm_grid, 256, gemm_smem>>>(x, Wq, bq, Wk, bk, Wv, bv);

    stats_finalize_kernel<<<dim3(3, BB), 256>>>();

    dim3 attn_grid(NTILES, BB);
    attn_kernel<<<attn_grid, 256, attn_smem>>>();

    reduce1_kernel<<<dim3(BB, 16), 256>>>();
    reduce2_kernel<<<BB, 256>>>(out);
}